// round 9
// baseline (speedup 1.0000x reference)
#include <cuda_runtime.h>

#define C_IN 256
#define O_OUT 256
#define CKTOT 2304   // C_IN * 9

// Duplicated transposed deform weights: wT2[ck][o] = {w,w}, ck = c*9+k.
// Row = 256 float2 = 2048 bytes = 128 ulonglong2.
__device__ float2 g_wT2_T[CKTOT * O_OUT];
__device__ float2 g_wT2_S[CKTOT * O_OUT];

// Split-C partial sums for the offset convs (G=8 both).
__device__ float g_part_S[8 * 16 * 18 * 1024];
__device__ float g_part_T[8 * 16 * 18 * 256];

// ---------------------------------------------------------------------------
// Merged weight transpose+duplicate: w[o][c][3][3] -> wT2[c*9+k][o] = {w,w}
// grid = 2*CKTOT blocks; first CKTOT = T branch, rest = S branch.
// ---------------------------------------------------------------------------
__global__ void transpose_dup_kernel(const float* __restrict__ wT_src,
                                     const float* __restrict__ wS_src) {
    int blk = blockIdx.x;
    const float* w = (blk < CKTOT) ? wT_src : wS_src;
    float2* wT2    = (blk < CKTOT) ? g_wT2_T : g_wT2_S;
    int ck = (blk < CKTOT) ? blk : blk - CKTOT;
    int o = threadIdx.x;
    float v = w[o * CKTOT + ck];
    wT2[ck * O_OUT + o] = make_float2(v, v);
}

// ---------------------------------------------------------------------------
// Offset conv partial: 3x3, stride 1, pad 1, CG-channel slice of 256->18.
// ---------------------------------------------------------------------------
template <int H, int W, int G>
__device__ __forceinline__ void offset_conv_part_body(
    const float* __restrict__ x, const float* __restrict__ wgt,
    float* __restrict__ part, int blk,
    float* sx /*8*324*/, float* sw /*18*72*/)
{
    const int HW = H * W;
    const int tiles = (H / 16) * (W / 16);
    const int CG = C_IN / G;

    const int b    = blk / (tiles * G);
    int rem        = blk % (tiles * G);
    const int tile = rem / G;
    const int g    = rem % G;
    const int h0 = (tile / (W / 16)) * 16;
    const int w0 = (tile % (W / 16)) * 16;
    const int c_start = g * CG;

    const int tid = threadIdx.x;
    const int ty = tid >> 4, tx = tid & 15;

    float acc[18];
#pragma unroll
    for (int i = 0; i < 18; i++) acc[i] = 0.f;

    const float* xb = x + (size_t)b * C_IN * HW;

    for (int c0 = c_start; c0 < c_start + CG; c0 += 8) {
        __syncthreads();
        for (int e = tid; e < 8 * 324; e += 256) {
            int c = e / 324, r = e % 324;
            int yy = r / 18 - 1 + h0;
            int xx = r % 18 - 1 + w0;
            float v = 0.f;
            if (yy >= 0 && yy < H && xx >= 0 && xx < W)
                v = xb[(c0 + c) * HW + yy * W + xx];
            sx[e] = v;
        }
        for (int e = tid; e < 18 * 72; e += 256) {
            int oc = e / 72, r = e % 72;
            sw[e] = wgt[oc * CKTOT + c0 * 9 + r];
        }
        __syncthreads();

#pragma unroll
        for (int c = 0; c < 8; c++) {
            float xv[9];
#pragma unroll
            for (int t = 0; t < 9; t++)
                xv[t] = sx[c * 324 + (ty + t / 3) * 18 + (tx + t % 3)];
#pragma unroll
            for (int oc = 0; oc < 18; oc++) {
#pragma unroll
                for (int t = 0; t < 9; t++)
                    acc[oc] += xv[t] * sw[oc * 72 + c * 9 + t];
            }
        }
    }

    const int h = h0 + ty, w = w0 + tx;
    float* ob = part + (size_t)g * 16 * 18 * HW + (size_t)b * 18 * HW + h * W + w;
#pragma unroll
    for (int oc = 0; oc < 18; oc++)
        ob[oc * HW] = acc[oc];
}

// Merged: blocks 0..511 = search (32x32), 512..639 = kernel (16x16).
__global__ void __launch_bounds__(256) offset_conv_merged_kernel(
    const float* __restrict__ xT, const float* __restrict__ wgtT,
    const float* __restrict__ xS, const float* __restrict__ wgtS)
{
    __shared__ float sx[8 * 324];
    __shared__ float sw[18 * 72];
    int blk = blockIdx.x;
    if (blk < 512)
        offset_conv_part_body<32, 32, 8>(xS, wgtS, g_part_S, blk, sx, sw);
    else
        offset_conv_part_body<16, 16, 8>(xT, wgtT, g_part_T, blk - 512, sx, sw);
}

// ---------------------------------------------------------------------------
// Merged reduce partials + bias -> final offset tensors (d_out regions).
// Elements: [0, 73728) = T (HW=256), [73728, 368640) = S (HW=1024).
// ---------------------------------------------------------------------------
__global__ void reduce_offset_merged_kernel(
    const float* __restrict__ biasT, float* __restrict__ outT,
    const float* __restrict__ biasS, float* __restrict__ outS)
{
    int i = blockIdx.x * 256 + threadIdx.x;
    const float* part;
    const float* bias;
    float* out;
    int perG, HW, idx;
    if (i < 73728) {
        part = g_part_T; bias = biasT; out = outT;
        perG = 73728; HW = 256; idx = i;
    } else {
        if (i >= 368640) return;
        part = g_part_S; bias = biasS; out = outS;
        perG = 294912; HW = 1024; idx = i - 73728;
    }
    float s = 0.f;
#pragma unroll
    for (int g = 0; g < 8; g++) s += part[(size_t)g * perG + idx];
    int oc = (idx / HW) % 18;
    out[idx] = s + bias[oc];
}

// ---------------------------------------------------------------------------
// Deformable conv v1 (3x3, pad 1, 1 group, no bias). P=32 pixels per block.
// Phase 0: bilinear corner idx/weights (float4/int4) -> smem.
// Phase 1: gather samp[576][32] for a 64-channel chunk.
// Phase 2: register-blocked GEMM, pre-duplicated weights, f32x2 FMAs.
//   Thread tile: 4 out-ch {2oG, 2oG+1, 2oG+128, 2oG+129} x 8 pixels.
// ---------------------------------------------------------------------------
template <int H, int W>
__device__ __forceinline__ void deform_conv_body(
    const float* __restrict__ x, const float* __restrict__ off,
    const float2* __restrict__ wT2, float* __restrict__ out,
    int blk, float* smem)
{
    const int HW = H * W;
    const int nT = HW / 32;
    const int b = blk / nT;
    const int tileBase = (blk % nT) * 32;

    float*  samp = smem;                               // 576*32 floats
    float4* cWv  = (float4*)(smem + 576 * 32);         // 288 float4
    int4*   cIv  = (int4*)(cWv + 288);                 // 288 int4

    const int tid = threadIdx.x;

    // ---- Phase 0: bilinear corners for 9 taps x 32 positions ----
    for (int e = tid; e < 288; e += 256) {
        int k = e >> 5, p = e & 31;
        int pos = tileBase + p;
        int h = pos / W, w = pos % W;
        const float* ob = off + (size_t)b * 18 * HW + pos;
        float dy = ob[(2 * k) * HW];
        float dx = ob[(2 * k + 1) * HW];
        float sy = (float)(h + k / 3 - 1) + dy;
        float sx = (float)(w + k % 3 - 1) + dx;
        float fy = floorf(sy), fx = floorf(sx);
        int iy = (int)fy, ix = (int)fx;
        float ly = sy - fy, lx = sx - fx;
        float wb[4];
        wb[0] = (1.f - ly) * (1.f - lx);
        wb[1] = (1.f - ly) * lx;
        wb[2] = ly * (1.f - lx);
        wb[3] = ly * lx;
        int ic[4];
        float wc[4];
#pragma unroll
        for (int j = 0; j < 4; j++) {
            int yy = iy + (j >> 1);
            int xx = ix + (j & 1);
            bool ok = (yy >= 0) && (yy < H) && (xx >= 0) && (xx < W);
            int yc = min(max(yy, 0), H - 1);
            int xc = min(max(xx, 0), W - 1);
            ic[j] = yc * W + xc;
            wc[j] = ok ? wb[j] : 0.f;
        }
        cWv[e] = make_float4(wc[0], wc[1], wc[2], wc[3]);
        cIv[e] = make_int4(ic[0], ic[1], ic[2], ic[3]);
    }

    const int pG = tid >> 6;   // 0..3 -> pixels pG*8..+7
    const int oG = tid & 63;   // 0..63 -> channels {2oG,2oG+1,128+2oG,129+2oG}

    unsigned long long acc2[16];   // [j][i2]
#pragma unroll
    for (int i = 0; i < 16; i++) acc2[i] = 0ULL;

    const float* xb = x + (size_t)b * C_IN * HW;

    for (int c0 = 0; c0 < C_IN; c0 += 64) {
        __syncthreads();

        // ---- Phase 1: gather samp tile (64 ch x 9 taps) x 32 positions ----
        for (int e = tid; e < 576 * 32; e += 256) {
            int ck = e >> 5, p = e & 31;
            int cq = ck / 9;
            int k = ck - cq * 9;
            const float* xc = xb + (c0 + cq) * HW;
            float4 w4 = cWv[k * 32 + p];
            int4   i4 = cIv[k * 32 + p];
            samp[e] = w4.x * __ldg(xc + i4.x)
                    + w4.y * __ldg(xc + i4.y)
                    + w4.z * __ldg(xc + i4.z)
                    + w4.w * __ldg(xc + i4.w);
        }
        __syncthreads();

        // ---- Phase 2: f32x2 GEMM; dup-weight LDG.128s, broadcast LDS.128s ----
        // UNITS: wT2 row = 256 float2 = 2048 B = 128 ulonglong2.
        //   wA = wrow[ckl*128 + oG]       -> channels {2oG, 2oG+1}
        //   wB = wrow[ckl*128 + 64 + oG]  -> channels {128+2oG, 129+2oG}
        // samp row = 32 floats = 128 B = 8 ulonglong2; sp offset by pG*8 floats.
        const ulonglong2* wrow = (const ulonglong2*)(wT2 + (size_t)(c0 * 9) * O_OUT) + oG;
        const ulonglong2* sp = (const ulonglong2*)(samp + pG * 8);
#pragma unroll 4
        for (int ckl = 0; ckl < 576; ckl++) {
            ulonglong2 wA = __ldg(wrow + (size_t)ckl * 128);        // {w(2oG)x2, w(2oG+1)x2}
            ulonglong2 wB = __ldg(wrow + (size_t)ckl * 128 + 64);   // {w(128+2oG)x2, w(129+2oG)x2}
            ulonglong2 sA = sp[ckl * 8];                            // pixels pG*8+0..3
            ulonglong2 sB = sp[ckl * 8 + 1];                        // pixels pG*8+4..7
            asm("fma.rn.f32x2 %0, %1, %2, %0;" : "+l"(acc2[0])  : "l"(wA.x), "l"(sA.x));
            asm("fma.rn.f32x2 %0, %1, %2, %0;" : "+l"(acc2[1])  : "l"(wA.x), "l"(sA.y));
            asm("fma.rn.f32x2 %0, %1, %2, %0;" : "+l"(acc2[2])  : "l"(wA.x), "l"(sB.x));
            asm("fma.rn.f32x2 %0, %1, %2, %0;" : "+l"(acc2[3])  : "l"(wA.x), "l"(sB.y));
            asm("fma.rn.f32x2 %0, %1, %2, %0;" : "+l"(acc2[4])  : "l"(wA.y), "l"(sA.x));
            asm("fma.rn.f32x2 %0, %1, %2, %0;" : "+l"(acc2[5])  : "l"(wA.y), "l"(sA.y));
            asm("fma.rn.f32x2 %0, %1, %2, %0;" : "+l"(acc2[6])  : "l"(wA.y), "l"(sB.x));
            asm("fma.rn.f32x2 %0, %1, %2, %0;" : "+l"(acc2[7])  : "l"(wA.y), "l"(sB.y));
            asm("fma.rn.f32x2 %0, %1, %2, %0;" : "+l"(acc2[8])  : "l"(wB.x), "l"(sA.x));
            asm("fma.rn.f32x2 %0, %1, %2, %0;" : "+l"(acc2[9])  : "l"(wB.x), "l"(sA.y));
            asm("fma.rn.f32x2 %0, %1, %2, %0;" : "+l"(acc2[10]) : "l"(wB.x), "l"(sB.x));
            asm("fma.rn.f32x2 %0, %1, %2, %0;" : "+l"(acc2[11]) : "l"(wB.x), "l"(sB.y));
            asm("fma.rn.f32x2 %0, %1, %2, %0;" : "+l"(acc2[12]) : "l"(wB.y), "l"(sA.x));
            asm("fma.rn.f32x2 %0, %1, %2, %0;" : "+l"(acc2[13]) : "l"(wB.y), "l"(sA.y));
            asm("fma.rn.f32x2 %0, %1, %2, %0;" : "+l"(acc2[14]) : "l"(wB.y), "l"(sB.x));
            asm("fma.rn.f32x2 %0, %1, %2, %0;" : "+l"(acc2[15]) : "l"(wB.y), "l"(sB.y));
        }
    }

    // ---- Epilogue: stage through smem (o x p, pad 33) for coalesced stores ----
    __syncthreads();
    float* sAcc = smem;   // 256*33 floats fits in samp area
#pragma unroll
    for (int j = 0; j < 4; j++) {
        int o = 2 * oG + (j & 1) + (j >> 1) * 128;
#pragma unroll
        for (int i2 = 0; i2 < 4; i2++) {
            unsigned lo, hi;
            asm("mov.b64 {%0, %1}, %2;" : "=r"(lo), "=r"(hi) : "l"(acc2[j * 4 + i2]));
            sAcc[o * 33 + pG * 8 + 2 * i2 + 0] = __uint_as_float(lo);
            sAcc[o * 33 + pG * 8 + 2 * i2 + 1] = __uint_as_float(hi);
        }
    }
    __syncthreads();

    float* ob = out + (size_t)b * O_OUT * HW + tileBase;
    const int po = tid & 31;
    const int ro = tid >> 5;
#pragma unroll 8
    for (int r = 0; r < 32; r++) {
        int o = r * 8 + ro;
        ob[(size_t)o * HW + po] = sAcc[o * 33 + po];
    }
}

// Merged: blocks 0..511 = search (32x32), 512..639 = kernel (16x16).
__global__ void __launch_bounds__(256, 2) deform_conv_merged_kernel(
    const float* __restrict__ xT, const float* __restrict__ offT, float* __restrict__ outT,
    const float* __restrict__ xS, const float* __restrict__ offS, float* __restrict__ outS)
{
    extern __shared__ float smem[];
    int blk = blockIdx.x;
    if (blk < 512)
        deform_conv_body<32, 32>(xS, offS, g_wT2_S, outS, blk, smem);
    else
        deform_conv_body<16, 16>(xT, offT, g_wT2_T, outT, blk - 512, smem);
}

// ---------------------------------------------------------------------------
// Launch
// ---------------------------------------------------------------------------
extern "C" void kernel_launch(void* const* d_in, const int* in_sizes, int n_in,
                              void* d_out, int out_size)
{
    const float* kernel_in = (const float*)d_in[0];  // 16x256x16x16
    const float* search_in = (const float*)d_in[1];  // 16x256x32x32
    const float* Toffset_w = (const float*)d_in[2];  // 18x256x3x3
    const float* Toffset_b = (const float*)d_in[3];  // 18
    const float* Tdeform_w = (const float*)d_in[4];  // 256x256x3x3
    const float* Soffset_w = (const float*)d_in[5];
    const float* Soffset_b = (const float*)d_in[6];
    const float* Sdeform_w = (const float*)d_in[7];

    float* out = (float*)d_out;
    float* kout = out;                       // 16*256*16*16 = 1,048,576
    float* sout = out + 1048576;             // 16*256*32*32 = 4,194,304
    float* koff = out + 5242880;             // 16*18*16*16  = 73,728
    float* soff = out + 5316608;             // 16*18*32*32  = 294,912

    const int smemD = (576 * 32) * 4 + 288 * 16 + 288 * 16;   // 82,944 B
    static int attr_done = 0;
    if (!attr_done) {
        cudaFuncSetAttribute((const void*)deform_conv_merged_kernel,
                             cudaFuncAttributeMaxDynamicSharedMemorySize, smemD);
        attr_done = 1;
    }

    // 1) weight transpose + duplicate (both branches)
    transpose_dup_kernel<<<2 * CKTOT, 256>>>(Tdeform_w, Sdeform_w);

    // 2) offset convs (merged, split-C partials)
    offset_conv_merged_kernel<<<640, 256>>>(kernel_in, Toffset_w, search_in, Soffset_w);

    // 3) reduce partials + bias into d_out offset regions (merged)
    reduce_offset_merged_kernel<<<(368640 + 255) / 256, 256>>>(
        Toffset_b, koff, Soffset_b, soff);

    // 4) deformable convs (merged; search blocks first)
    deform_conv_merged_kernel<<<640, 256, smemD>>>(
        kernel_in, koff, kout, search_in, soff, sout);
}

// round 11
// speedup vs baseline: 1.1771x; 1.1771x over previous
#include <cuda_runtime.h>

#define C_IN 256
#define O_OUT 256
#define CKTOT 2304   // C_IN * 9

// Transposed deform weights: wT[ck][o], ck = c*9+k.
// UNITS: row = 256 floats = 1024 B = 64 float4.
__device__ float g_wT_T[CKTOT * O_OUT];
__device__ float g_wT_S[CKTOT * O_OUT];

// Split-C partial sums for the offset convs (G=8 both).
__device__ float g_part_S[8 * 16 * 18 * 1024];
__device__ float g_part_T[8 * 16 * 18 * 256];

// ---------------------------------------------------------------------------
// Merged weight transpose: w[o][c][3][3] -> wT[c*9+k][o]
// grid = 2*CKTOT blocks; first CKTOT = T branch, rest = S branch.
// ---------------------------------------------------------------------------
__global__ void transpose_w_kernel(const float* __restrict__ wT_src,
                                   const float* __restrict__ wS_src) {
    int blk = blockIdx.x;
    const float* w = (blk < CKTOT) ? wT_src : wS_src;
    float* wT      = (blk < CKTOT) ? g_wT_T : g_wT_S;
    int ck = (blk < CKTOT) ? blk : blk - CKTOT;
    int o = threadIdx.x;
    wT[ck * O_OUT + o] = w[o * CKTOT + ck];
}

// ---------------------------------------------------------------------------
// Offset conv partial: 3x3, stride 1, pad 1, CG-channel slice of 256->18.
// ---------------------------------------------------------------------------
template <int H, int W, int G>
__device__ __forceinline__ void offset_conv_part_body(
    const float* __restrict__ x, const float* __restrict__ wgt,
    float* __restrict__ part, int blk,
    float* sx /*8*324*/, float* sw /*18*72*/)
{
    const int HW = H * W;
    const int tiles = (H / 16) * (W / 16);
    const int CG = C_IN / G;

    const int b    = blk / (tiles * G);
    int rem        = blk % (tiles * G);
    const int tile = rem / G;
    const int g    = rem % G;
    const int h0 = (tile / (W / 16)) * 16;
    const int w0 = (tile % (W / 16)) * 16;
    const int c_start = g * CG;

    const int tid = threadIdx.x;
    const int ty = tid >> 4, tx = tid & 15;

    float acc[18];
#pragma unroll
    for (int i = 0; i < 18; i++) acc[i] = 0.f;

    const float* xb = x + (size_t)b * C_IN * HW;

    for (int c0 = c_start; c0 < c_start + CG; c0 += 8) {
        __syncthreads();
        for (int e = tid; e < 8 * 324; e += 256) {
            int c = e / 324, r = e % 324;
            int yy = r / 18 - 1 + h0;
            int xx = r % 18 - 1 + w0;
            float v = 0.f;
            if (yy >= 0 && yy < H && xx >= 0 && xx < W)
                v = xb[(c0 + c) * HW + yy * W + xx];
            sx[e] = v;
        }
        for (int e = tid; e < 18 * 72; e += 256) {
            int oc = e / 72, r = e % 72;
            sw[e] = wgt[oc * CKTOT + c0 * 9 + r];
        }
        __syncthreads();

#pragma unroll
        for (int c = 0; c < 8; c++) {
            float xv[9];
#pragma unroll
            for (int t = 0; t < 9; t++)
                xv[t] = sx[c * 324 + (ty + t / 3) * 18 + (tx + t % 3)];
#pragma unroll
            for (int oc = 0; oc < 18; oc++) {
#pragma unroll
                for (int t = 0; t < 9; t++)
                    acc[oc] += xv[t] * sw[oc * 72 + c * 9 + t];
            }
        }
    }

    const int h = h0 + ty, w = w0 + tx;
    float* ob = part + (size_t)g * 16 * 18 * HW + (size_t)b * 18 * HW + h * W + w;
#pragma unroll
    for (int oc = 0; oc < 18; oc++)
        ob[oc * HW] = acc[oc];
}

// Merged: blocks 0..511 = search (32x32), 512..639 = kernel (16x16).
__global__ void __launch_bounds__(256) offset_conv_merged_kernel(
    const float* __restrict__ xT, const float* __restrict__ wgtT,
    const float* __restrict__ xS, const float* __restrict__ wgtS)
{
    __shared__ float sx[8 * 324];
    __shared__ float sw[18 * 72];
    int blk = blockIdx.x;
    if (blk < 512)
        offset_conv_part_body<32, 32, 8>(xS, wgtS, g_part_S, blk, sx, sw);
    else
        offset_conv_part_body<16, 16, 8>(xT, wgtT, g_part_T, blk - 512, sx, sw);
}

// ---------------------------------------------------------------------------
// Merged reduce partials + bias -> final offset tensors (d_out regions).
// ---------------------------------------------------------------------------
__global__ void reduce_offset_merged_kernel(
    const float* __restrict__ biasT, float* __restrict__ outT,
    const float* __restrict__ biasS, float* __restrict__ outS)
{
    int i = blockIdx.x * 256 + threadIdx.x;
    const float* part;
    const float* bias;
    float* out;
    int perG, HW, idx;
    if (i < 73728) {
        part = g_part_T; bias = biasT; out = outT;
        perG = 73728; HW = 256; idx = i;
    } else {
        if (i >= 368640) return;
        part = g_part_S; bias = biasS; out = outS;
        perG = 294912; HW = 1024; idx = i - 73728;
    }
    float s = 0.f;
#pragma unroll
    for (int g = 0; g < 8; g++) s += part[(size_t)g * perG + idx];
    int oc = (idx / HW) % 18;
    out[idx] = s + bias[oc];
}

// ---------------------------------------------------------------------------
// Deformable conv v1 (3x3, pad 1, 1 group, no bias). P=32 pixels per block.
// Channel chunk = 32 (8 chunks) so smem = 46,080 B -> 4 CTAs/SM (32 warps).
// Phase 0: bilinear corner idx/weights (float4/int4) -> smem.
// Phase 1: gather samp[288][32] per chunk.
// Phase 2: thread = 4 out-ch (4oG..4oG+3) x 8 pixels; f32x2 FMAs.
// Dynamic smem: samp[288*32] | cWv[288 float4] | cIv[288 int4] = 46,080 B
// ---------------------------------------------------------------------------
template <int H, int W>
__device__ __forceinline__ void deform_conv_body(
    const float* __restrict__ x, const float* __restrict__ off,
    const float* __restrict__ wT, float* __restrict__ out,
    int blk, float* smem)
{
    const int HW = H * W;
    const int nT = HW / 32;
    const int b = blk / nT;
    const int tileBase = (blk % nT) * 32;

    float*  samp = smem;                               // 288*32 floats = 36,864 B
    float4* cWv  = (float4*)(smem + 288 * 32);         // 288 float4
    int4*   cIv  = (int4*)(cWv + 288);                 // 288 int4

    const int tid = threadIdx.x;

    // ---- Phase 0: bilinear corners for 9 taps x 32 positions ----
    for (int e = tid; e < 288; e += 256) {
        int k = e >> 5, p = e & 31;
        int pos = tileBase + p;
        int h = pos / W, w = pos % W;
        const float* ob = off + (size_t)b * 18 * HW + pos;
        float dy = ob[(2 * k) * HW];
        float dx = ob[(2 * k + 1) * HW];
        float sy = (float)(h + k / 3 - 1) + dy;
        float sx = (float)(w + k % 3 - 1) + dx;
        float fy = floorf(sy), fx = floorf(sx);
        int iy = (int)fy, ix = (int)fx;
        float ly = sy - fy, lx = sx - fx;
        float wb[4];
        wb[0] = (1.f - ly) * (1.f - lx);
        wb[1] = (1.f - ly) * lx;
        wb[2] = ly * (1.f - lx);
        wb[3] = ly * lx;
        int ic[4];
        float wc[4];
#pragma unroll
        for (int j = 0; j < 4; j++) {
            int yy = iy + (j >> 1);
            int xx = ix + (j & 1);
            bool ok = (yy >= 0) && (yy < H) && (xx >= 0) && (xx < W);
            int yc = min(max(yy, 0), H - 1);
            int xc = min(max(xx, 0), W - 1);
            ic[j] = yc * W + xc;
            wc[j] = ok ? wb[j] : 0.f;
        }
        cWv[e] = make_float4(wc[0], wc[1], wc[2], wc[3]);
        cIv[e] = make_int4(ic[0], ic[1], ic[2], ic[3]);
    }

    const int pG = tid >> 6;   // 0..3 -> pixels pG*8..+7
    const int oG = tid & 63;   // 0..63 -> channels 4oG..4oG+3

    unsigned long long acc2[16];   // [j][i2]: j = out-ch 0..3, i2 = pixel pair 0..3
#pragma unroll
    for (int i = 0; i < 16; i++) acc2[i] = 0ULL;

    const float* xb = x + (size_t)b * C_IN * HW;

    for (int c0 = 0; c0 < C_IN; c0 += 32) {
        __syncthreads();

        // ---- Phase 1: gather samp tile (32 ch x 9 taps) x 32 positions ----
        for (int e = tid; e < 288 * 32; e += 256) {
            int ck = e >> 5, p = e & 31;
            int cq = ck / 9;
            int k = ck - cq * 9;
            const float* xc = xb + (c0 + cq) * HW;
            float4 w4 = cWv[k * 32 + p];
            int4   i4 = cIv[k * 32 + p];
            samp[e] = w4.x * __ldg(xc + i4.x)
                    + w4.y * __ldg(xc + i4.y)
                    + w4.z * __ldg(xc + i4.z)
                    + w4.w * __ldg(xc + i4.w);
        }
        __syncthreads();

        // ---- Phase 2: f32x2 GEMM ----
        // UNITS: wT row = 256 floats = 64 float4; wp bump = +64/ckl.
        //        samp row = 32 floats = 8 ulonglong2; sp bump = +8/ckl.
        const float4* wp = (const float4*)(wT + (size_t)(c0 * 9) * O_OUT) + oG;
        const ulonglong2* sp = (const ulonglong2*)(samp + pG * 8);
#pragma unroll 4
        for (int ckl = 0; ckl < 288; ckl++) {
            float4 w4 = __ldg(wp);  wp += 64;          // ch 4oG..4oG+3 (LDG.128)
            ulonglong2 sA = sp[0];                     // pixels pG*8+0..3 (LDS.128)
            ulonglong2 sB = sp[1];  sp += 8;           // pixels pG*8+4..7 (LDS.128)
            unsigned long long w2[4];
            asm("mov.b64 %0, {%1, %1};" : "=l"(w2[0]) : "r"(__float_as_uint(w4.x)));
            asm("mov.b64 %0, {%1, %1};" : "=l"(w2[1]) : "r"(__float_as_uint(w4.y)));
            asm("mov.b64 %0, {%1, %1};" : "=l"(w2[2]) : "r"(__float_as_uint(w4.z)));
            asm("mov.b64 %0, {%1, %1};" : "=l"(w2[3]) : "r"(__float_as_uint(w4.w)));
#pragma unroll
            for (int j = 0; j < 4; j++) {
                asm("fma.rn.f32x2 %0, %1, %2, %0;" : "+l"(acc2[j * 4 + 0]) : "l"(w2[j]), "l"(sA.x));
                asm("fma.rn.f32x2 %0, %1, %2, %0;" : "+l"(acc2[j * 4 + 1]) : "l"(w2[j]), "l"(sA.y));
                asm("fma.rn.f32x2 %0, %1, %2, %0;" : "+l"(acc2[j * 4 + 2]) : "l"(w2[j]), "l"(sB.x));
                asm("fma.rn.f32x2 %0, %1, %2, %0;" : "+l"(acc2[j * 4 + 3]) : "l"(w2[j]), "l"(sB.y));
            }
        }
    }

    // ---- Epilogue: stage through smem (o x p, pad 33) for coalesced stores ----
    __syncthreads();
    float* sAcc = smem;   // 256*33 = 8448 floats = 33.8 KB <= samp area (36.9 KB)
#pragma unroll
    for (int j = 0; j < 4; j++) {
        int o = oG * 4 + j;
#pragma unroll
        for (int i2 = 0; i2 < 4; i2++) {
            unsigned lo, hi;
            asm("mov.b64 {%0, %1}, %2;" : "=r"(lo), "=r"(hi) : "l"(acc2[j * 4 + i2]));
            sAcc[o * 33 + pG * 8 + 2 * i2 + 0] = __uint_as_float(lo);
            sAcc[o * 33 + pG * 8 + 2 * i2 + 1] = __uint_as_float(hi);
        }
    }
    __syncthreads();

    float* ob = out + (size_t)b * O_OUT * HW + tileBase;
    const int po = tid & 31;
    const int ro = tid >> 5;
#pragma unroll 8
    for (int r = 0; r < 32; r++) {
        int o = r * 8 + ro;
        ob[(size_t)o * HW + po] = sAcc[o * 33 + po];
    }
}

// Merged: blocks 0..511 = search (32x32), 512..639 = kernel (16x16).
__global__ void __launch_bounds__(256, 4) deform_conv_merged_kernel(
    const float* __restrict__ xT, const float* __restrict__ offT, float* __restrict__ outT,
    const float* __restrict__ xS, const float* __restrict__ offS, float* __restrict__ outS)
{
    extern __shared__ float smem[];
    int blk = blockIdx.x;
    if (blk < 512)
        deform_conv_body<32, 32>(xS, offS, g_wT_S, outS, blk, smem);
    else
        deform_conv_body<16, 16>(xT, offT, g_wT_T, outT, blk - 512, smem);
}

// ---------------------------------------------------------------------------
// Launch
// ---------------------------------------------------------------------------
extern "C" void kernel_launch(void* const* d_in, const int* in_sizes, int n_in,
                              void* d_out, int out_size)
{
    const float* kernel_in = (const float*)d_in[0];  // 16x256x16x16
    const float* search_in = (const float*)d_in[1];  // 16x256x32x32
    const float* Toffset_w = (const float*)d_in[2];  // 18x256x3x3
    const float* Toffset_b = (const float*)d_in[3];  // 18
    const float* Tdeform_w = (const float*)d_in[4];  // 256x256x3x3
    const float* Soffset_w = (const float*)d_in[5];
    const float* Soffset_b = (const float*)d_in[6];
    const float* Sdeform_w = (const float*)d_in[7];

    float* out = (float*)d_out;
    float* kout = out;                       // 16*256*16*16 = 1,048,576
    float* sout = out + 1048576;             // 16*256*32*32 = 4,194,304
    float* koff = out + 5242880;             // 16*18*16*16  = 73,728
    float* soff = out + 5316608;             // 16*18*32*32  = 294,912

    const int smemD = (288 * 32) * 4 + 288 * 16 + 288 * 16;   // 46,080 B
    static int attr_done = 0;
    if (!attr_done) {
        cudaFuncSetAttribute((const void*)deform_conv_merged_kernel,
                             cudaFuncAttributeMaxDynamicSharedMemorySize, smemD);
        attr_done = 1;
    }

    // 1) weight transposes (both branches)
    transpose_w_kernel<<<2 * CKTOT, 256>>>(Tdeform_w, Sdeform_w);

    // 2) offset convs (merged, split-C partials)
    offset_conv_merged_kernel<<<640, 256>>>(kernel_in, Toffset_w, search_in, Soffset_w);

    // 3) reduce partials + bias into d_out offset regions (merged)
    reduce_offset_merged_kernel<<<(368640 + 255) / 256, 256>>>(
        Toffset_b, koff, Soffset_b, soff);

    // 4) deformable convs (merged; search blocks first)
    deform_conv_merged_kernel<<<640, 256, smemD>>>(
        kernel_in, koff, kout, search_in, soff, sout);
}